// round 1
// baseline (speedup 1.0000x reference)
#include <cuda_runtime.h>
#include <cuda_bf16.h>
#include <math.h>

// Problem constants
#define B 8
#define S 1025
#define E 1408
#define H 16
#define D 88
#define D2 44
#define M_ROWS (B * S)          // 8200

// ---------------------------------------------------------------------------
// Scratch (allocation-free: __device__ globals)
// ---------------------------------------------------------------------------
__device__ float g_q[(size_t)M_ROWS * E];
__device__ float g_k[(size_t)M_ROWS * E];
__device__ float g_v[(size_t)M_ROWS * E];
__device__ float g_attn[(size_t)M_ROWS * E];

// ---------------------------------------------------------------------------
// GEMM: C[m][n] = sum_k A[m][k] * W[n][k] + bias[n], optional interleaved RoPE
// A: M x E row-major, W: E x E row-major (N-major rows, K cols)
// Tile: BM=64, BN=64, BK=16, 256 threads, 4x4 micro-tile per thread.
// ---------------------------------------------------------------------------
#define BM 64
#define BN 64
#define BK 16

__global__ __launch_bounds__(256)
void gemm_bias_rope(const float* __restrict__ A,
                    const float* __restrict__ W,
                    const float* __restrict__ bias,
                    const float* __restrict__ fcos,
                    const float* __restrict__ fsin,
                    float* __restrict__ C,
                    int Mdim, int rope)
{
    __shared__ float As[BK][BM];   // k-major
    __shared__ float Bs[BK][BN];   // k-major

    const int tid = threadIdx.x;
    const int tx = tid % 16;
    const int ty = tid / 16;
    const int m0 = blockIdx.x * BM;
    const int n0 = blockIdx.y * BN;

    float acc[4][4] = {};

    const int lr = tid >> 2;       // 0..63 (row within tile for loads)
    const int kq = tid & 3;        // 0..3  (float4 index within BK)

    for (int k0 = 0; k0 < E; k0 += BK) {
        // Load A tile (guard rows) and W tile (always in range: N,K = 1408)
        float4 av;
        int am = m0 + lr;
        if (am < Mdim) {
            av = *(const float4*)&A[(size_t)am * E + k0 + kq * 4];
        } else {
            av = make_float4(0.f, 0.f, 0.f, 0.f);
        }
        As[kq * 4 + 0][lr] = av.x;
        As[kq * 4 + 1][lr] = av.y;
        As[kq * 4 + 2][lr] = av.z;
        As[kq * 4 + 3][lr] = av.w;

        float4 bv = *(const float4*)&W[(size_t)(n0 + lr) * E + k0 + kq * 4];
        Bs[kq * 4 + 0][lr] = bv.x;
        Bs[kq * 4 + 1][lr] = bv.y;
        Bs[kq * 4 + 2][lr] = bv.z;
        Bs[kq * 4 + 3][lr] = bv.w;

        __syncthreads();

#pragma unroll
        for (int kk = 0; kk < BK; kk++) {
            float4 a = *(const float4*)&As[kk][ty * 4];
            float4 b = *(const float4*)&Bs[kk][tx * 4];
            acc[0][0] += a.x * b.x; acc[0][1] += a.x * b.y;
            acc[0][2] += a.x * b.z; acc[0][3] += a.x * b.w;
            acc[1][0] += a.y * b.x; acc[1][1] += a.y * b.y;
            acc[1][2] += a.y * b.z; acc[1][3] += a.y * b.w;
            acc[2][0] += a.z * b.x; acc[2][1] += a.z * b.y;
            acc[2][2] += a.z * b.z; acc[2][3] += a.z * b.w;
            acc[3][0] += a.w * b.x; acc[3][1] += a.w * b.y;
            acc[3][2] += a.w * b.z; acc[3][3] += a.w * b.w;
        }
        __syncthreads();
    }

    // Epilogue: bias + optional RoPE (interleaved pairs within head dim)
    const int nbase = n0 + tx * 4;
    const float bb0 = bias[nbase + 0];
    const float bb1 = bias[nbase + 1];
    const float bb2 = bias[nbase + 2];
    const float bb3 = bias[nbase + 3];

#pragma unroll
    for (int i = 0; i < 4; i++) {
        int m = m0 + ty * 4 + i;
        if (m >= Mdim) continue;
        float v0 = acc[i][0] + bb0;
        float v1 = acc[i][1] + bb1;
        float v2 = acc[i][2] + bb2;
        float v3 = acc[i][3] + bb3;
        if (rope) {
            int s = m % S;
            int dd = nbase % D;              // even, multiple of 4
            int i0 = dd >> 1;
            float c0 = fcos[s * D2 + i0];
            float s0 = fsin[s * D2 + i0];
            float c1 = fcos[s * D2 + i0 + 1];
            float s1 = fsin[s * D2 + i0 + 1];
            float t0 = v0 * c0 - v1 * s0;
            v1       = v0 * s0 + v1 * c0;
            v0 = t0;
            float t2 = v2 * c1 - v3 * s1;
            v3       = v2 * s1 + v3 * c1;
            v2 = t2;
        }
        *(float4*)&C[(size_t)m * E + nbase] = make_float4(v0, v1, v2, v3);
    }
}

// ---------------------------------------------------------------------------
// Flash attention: warp-per-query, 32-key tiles, online softmax.
// grid = (ceil(S/8), B*H), block = 256 (8 warps)
// ---------------------------------------------------------------------------
#define TK 32
#define NW 8
#define KP 92   // smem pitch (floats): 92 -> conflict-free float4 rows

__global__ __launch_bounds__(256)
void flash_attn(const float* __restrict__ q,
                const float* __restrict__ k,
                const float* __restrict__ v,
                float* __restrict__ out)
{
    __shared__ float Ksh[TK][KP];
    __shared__ float Vsh[TK][KP];
    __shared__ float qsh[NW][KP];
    __shared__ float psh[NW][TK];

    const int bh = blockIdx.y;
    const int b  = bh / H;
    const int h  = bh % H;
    const int warp = threadIdx.x >> 5;
    const int lane = threadIdx.x & 31;
    const int qi = blockIdx.x * NW + warp;

    const float scale = rsqrtf((float)D);

    if (qi < S) {
        const float* qp = &q[((size_t)(b * S + qi)) * E + h * D];
        for (int d = lane; d < D; d += 32) qsh[warp][d] = qp[d] * scale;
    }

    float mrun = -1e30f, lrun = 0.f;
    float o0 = 0.f, o1 = 0.f, o2 = 0.f;

    for (int t0 = 0; t0 < S; t0 += TK) {
        __syncthreads();   // previous tile fully consumed

        // Cooperative K/V tile load (float4), zero-fill OOB keys
        for (int idx = threadIdx.x; idx < TK * (D / 4); idx += 256) {
            int r  = idx / (D / 4);
            int c4 = idx % (D / 4);
            int key = t0 + r;
            float4 kv, vv;
            if (key < S) {
                size_t base = ((size_t)(b * S + key)) * E + h * D + c4 * 4;
                kv = *(const float4*)&k[base];
                vv = *(const float4*)&v[base];
            } else {
                kv = make_float4(0.f, 0.f, 0.f, 0.f);
                vv = kv;
            }
            *(float4*)&Ksh[r][c4 * 4] = kv;
            *(float4*)&Vsh[r][c4 * 4] = vv;
        }
        __syncthreads();

        if (qi < S) {
            const int key = t0 + lane;
            float sc = 0.f;
#pragma unroll
            for (int c = 0; c < D / 4; c++) {
                float4 qv = *(const float4*)&qsh[warp][c * 4];
                float4 kv = *(const float4*)&Ksh[lane][c * 4];
                sc += qv.x * kv.x + qv.y * kv.y + qv.z * kv.z + qv.w * kv.w;
            }
            if (key >= S) sc = -1e30f;

            float mt = sc;
#pragma unroll
            for (int off = 16; off; off >>= 1)
                mt = fmaxf(mt, __shfl_xor_sync(0xffffffffu, mt, off));
            float mnew = fmaxf(mrun, mt);

            float p = (key < S) ? __expf(sc - mnew) : 0.f;
            float ps = p;
#pragma unroll
            for (int off = 16; off; off >>= 1)
                ps += __shfl_xor_sync(0xffffffffu, ps, off);

            float alpha = __expf(mrun - mnew);
            lrun = lrun * alpha + ps;
            psh[warp][lane] = p;
            __syncwarp();

            o0 *= alpha; o1 *= alpha; o2 *= alpha;
#pragma unroll
            for (int j = 0; j < TK; j++) {
                float pj = psh[warp][j];
                o0 += pj * Vsh[j][lane];
                o1 += pj * Vsh[j][lane + 32];
                if (lane < D - 64) o2 += pj * Vsh[j][lane + 64];
            }
            mrun = mnew;
            __syncwarp();
        }
    }

    if (qi < S) {
        float inv = 1.f / lrun;
        float* op = &out[((size_t)(b * S + qi)) * E + h * D];
        op[lane]      = o0 * inv;
        op[lane + 32] = o1 * inv;
        if (lane < D - 64) op[lane + 64] = o2 * inv;
    }
}

// ---------------------------------------------------------------------------
// Launch
// ---------------------------------------------------------------------------
extern "C" void kernel_launch(void* const* d_in, const int* in_sizes, int n_in,
                              void* d_out, int out_size)
{
    const float* hs   = (const float*)d_in[0];
    const float* fcos = (const float*)d_in[1];
    const float* fsin = (const float*)d_in[2];
    const float* Wq   = (const float*)d_in[3];
    const float* bq   = (const float*)d_in[4];
    const float* Wk   = (const float*)d_in[5];
    const float* bk   = (const float*)d_in[6];
    const float* Wv   = (const float*)d_in[7];
    const float* bv   = (const float*)d_in[8];
    const float* Wo   = (const float*)d_in[9];
    const float* bo   = (const float*)d_in[10];
    float* out = (float*)d_out;

    float *pq, *pk, *pv, *pa;
    cudaGetSymbolAddress((void**)&pq, g_q);
    cudaGetSymbolAddress((void**)&pk, g_k);
    cudaGetSymbolAddress((void**)&pv, g_v);
    cudaGetSymbolAddress((void**)&pa, g_attn);

    dim3 gg((M_ROWS + BM - 1) / BM, E / BN, 1);   // 129 x 22
    gemm_bias_rope<<<gg, 256>>>(hs, Wq, bq, fcos, fsin, pq, M_ROWS, 1);
    gemm_bias_rope<<<gg, 256>>>(hs, Wk, bk, fcos, fsin, pk, M_ROWS, 1);
    gemm_bias_rope<<<gg, 256>>>(hs, Wv, bv, fcos, fsin, pv, M_ROWS, 0);

    dim3 ga((S + NW - 1) / NW, B * H, 1);         // 129 x 128
    flash_attn<<<ga, 256>>>(pq, pk, pv, pa);

    gemm_bias_rope<<<gg, 256>>>(pa, Wo, bo, fcos, fsin, out, M_ROWS, 0);
}

// round 2
// speedup vs baseline: 1.7397x; 1.7397x over previous
#include <cuda_runtime.h>
#include <cuda_bf16.h>
#include <math.h>

// Problem constants
#define B 8
#define S 1025
#define E 1408
#define H 16
#define D 88
#define D2 44
#define M_ROWS (B * S)          // 8200

// ---------------------------------------------------------------------------
// Scratch (allocation-free: __device__ globals)
// ---------------------------------------------------------------------------
__device__ float g_q[(size_t)M_ROWS * E];
__device__ float g_k[(size_t)M_ROWS * E];
__device__ float g_v[(size_t)M_ROWS * E];
__device__ float g_attn[(size_t)M_ROWS * E];

// ---------------------------------------------------------------------------
// GEMM v2: C[m][n] = sum_k A[m][k] * W[n][k] + bias[n], optional RoPE.
// BM=BN=128, BK=8, 256 threads, 8x8 micro-tile (4+4 split), reg prefetch.
// ---------------------------------------------------------------------------
#define BM 128
#define BN 128
#define BK 8
#define PAD 4

__global__ __launch_bounds__(256)
void gemm_bias_rope(const float* __restrict__ A,
                    const float* __restrict__ W,
                    const float* __restrict__ bias,
                    const float* __restrict__ fcos,
                    const float* __restrict__ fsin,
                    float* __restrict__ C,
                    int Mdim, int rope)
{
    __shared__ float As[BK][BM + PAD];
    __shared__ float Bs[BK][BN + PAD];

    const int tid = threadIdx.x;
    const int tx = tid % 16;
    const int ty = tid / 16;
    const int m0 = blockIdx.x * BM;
    const int n0 = blockIdx.y * BN;

    const int lrow = tid >> 1;          // 0..127
    const int kq   = tid & 1;           // 0..1 (which float4 of the 8-wide k)

    float acc[8][8] = {};

    // prefetch tile 0
    float4 av, bv;
    {
        int am = m0 + lrow;
        av = (am < Mdim) ? *(const float4*)&A[(size_t)am * E + kq * 4]
                         : make_float4(0.f, 0.f, 0.f, 0.f);
        bv = *(const float4*)&W[(size_t)(n0 + lrow) * E + kq * 4];
    }

    for (int k0 = 0; k0 < E; k0 += BK) {
        // store prefetched tile to smem
        As[kq * 4 + 0][lrow] = av.x;
        As[kq * 4 + 1][lrow] = av.y;
        As[kq * 4 + 2][lrow] = av.z;
        As[kq * 4 + 3][lrow] = av.w;
        Bs[kq * 4 + 0][lrow] = bv.x;
        Bs[kq * 4 + 1][lrow] = bv.y;
        Bs[kq * 4 + 2][lrow] = bv.z;
        Bs[kq * 4 + 3][lrow] = bv.w;
        __syncthreads();

        // prefetch next tile while computing on current
        if (k0 + BK < E) {
            int am = m0 + lrow;
            av = (am < Mdim)
                 ? *(const float4*)&A[(size_t)am * E + k0 + BK + kq * 4]
                 : make_float4(0.f, 0.f, 0.f, 0.f);
            bv = *(const float4*)&W[(size_t)(n0 + lrow) * E + k0 + BK + kq * 4];
        }

#pragma unroll
        for (int kk = 0; kk < BK; kk++) {
            float4 a0 = *(const float4*)&As[kk][ty * 4];
            float4 a1 = *(const float4*)&As[kk][ty * 4 + 64];
            float4 b0 = *(const float4*)&Bs[kk][tx * 4];
            float4 b1 = *(const float4*)&Bs[kk][tx * 4 + 64];
            float ar[8] = {a0.x, a0.y, a0.z, a0.w, a1.x, a1.y, a1.z, a1.w};
            float br[8] = {b0.x, b0.y, b0.z, b0.w, b1.x, b1.y, b1.z, b1.w};
#pragma unroll
            for (int r = 0; r < 8; r++)
#pragma unroll
                for (int c = 0; c < 8; c++)
                    acc[r][c] += ar[r] * br[c];
        }
        __syncthreads();
    }

    // Epilogue: bias + optional RoPE, 4 float4 stores per row-subgroup
#pragma unroll
    for (int jh = 0; jh < 2; jh++) {
        const int nb = n0 + tx * 4 + jh * 64;
        const float bb0 = bias[nb + 0];
        const float bb1 = bias[nb + 1];
        const float bb2 = bias[nb + 2];
        const float bb3 = bias[nb + 3];
#pragma unroll
        for (int ih = 0; ih < 2; ih++) {
#pragma unroll
            for (int i = 0; i < 4; i++) {
                int m = m0 + ty * 4 + ih * 64 + i;
                if (m >= Mdim) continue;
                float v0 = acc[ih * 4 + i][jh * 4 + 0] + bb0;
                float v1 = acc[ih * 4 + i][jh * 4 + 1] + bb1;
                float v2 = acc[ih * 4 + i][jh * 4 + 2] + bb2;
                float v3 = acc[ih * 4 + i][jh * 4 + 3] + bb3;
                if (rope) {
                    int s = m % S;
                    int dd = nb % D;            // multiple of 4
                    int i0 = dd >> 1;
                    float c0 = fcos[s * D2 + i0];
                    float s0 = fsin[s * D2 + i0];
                    float c1 = fcos[s * D2 + i0 + 1];
                    float s1 = fsin[s * D2 + i0 + 1];
                    float t0 = v0 * c0 - v1 * s0;
                    v1       = v0 * s0 + v1 * c0;
                    v0 = t0;
                    float t2 = v2 * c1 - v3 * s1;
                    v3       = v2 * s1 + v3 * c1;
                    v2 = t2;
                }
                *(float4*)&C[(size_t)m * E + nb] = make_float4(v0, v1, v2, v3);
            }
        }
    }
}

// ---------------------------------------------------------------------------
// Flash attention v2: 4 queries per warp, 32-key tiles, online softmax.
// grid = (ceil(S/32), B*H), block = 256 (8 warps)
// ---------------------------------------------------------------------------
#define TK 32
#define NW 8
#define QPW 4
#define KP 92   // smem pitch (floats)

__global__ __launch_bounds__(256)
void flash_attn(const float* __restrict__ q,
                const float* __restrict__ k,
                const float* __restrict__ v,
                float* __restrict__ out)
{
    __shared__ float Ksh[TK][KP];
    __shared__ float Vsh[TK][KP];
    __shared__ float qsh[NW][QPW][KP];
    __shared__ float psh[NW][QPW][TK];

    const int bh = blockIdx.y;
    const int b  = bh / H;
    const int h  = bh % H;
    const int warp = threadIdx.x >> 5;
    const int lane = threadIdx.x & 31;
    const int q0 = (blockIdx.x * NW + warp) * QPW;

    const float scale = rsqrtf((float)D);

#pragma unroll
    for (int qq = 0; qq < QPW; qq++) {
        int qi = q0 + qq;
        if (qi < S) {
            const float* qp = &q[((size_t)(b * S + qi)) * E + h * D];
            for (int d = lane; d < D; d += 32)
                qsh[warp][qq][d] = qp[d] * scale;
        } else {
            for (int d = lane; d < D; d += 32)
                qsh[warp][qq][d] = 0.f;
        }
    }

    float mrun[QPW], lrun[QPW], o[QPW][3];
#pragma unroll
    for (int qq = 0; qq < QPW; qq++) {
        mrun[qq] = -1e30f; lrun[qq] = 0.f;
        o[qq][0] = o[qq][1] = o[qq][2] = 0.f;
    }

    for (int t0 = 0; t0 < S; t0 += TK) {
        __syncthreads();   // previous tile fully consumed

        // Cooperative K/V tile load (float4), zero-fill OOB keys
        for (int idx = threadIdx.x; idx < TK * (D / 4); idx += 256) {
            int r  = idx / (D / 4);
            int c4 = idx % (D / 4);
            int key = t0 + r;
            float4 kv, vv;
            if (key < S) {
                size_t base = ((size_t)(b * S + key)) * E + h * D + c4 * 4;
                kv = *(const float4*)&k[base];
                vv = *(const float4*)&v[base];
            } else {
                kv = make_float4(0.f, 0.f, 0.f, 0.f);
                vv = kv;
            }
            *(float4*)&Ksh[r][c4 * 4] = kv;
            *(float4*)&Vsh[r][c4 * 4] = vv;
        }
        __syncthreads();

        const int key = t0 + lane;
        const bool kin = (key < S);

        float sc[QPW] = {0.f, 0.f, 0.f, 0.f};
#pragma unroll
        for (int c = 0; c < D / 4; c++) {
            float4 kv = *(const float4*)&Ksh[lane][c * 4];
#pragma unroll
            for (int qq = 0; qq < QPW; qq++) {
                float4 qv = *(const float4*)&qsh[warp][qq][c * 4];
                sc[qq] += qv.x * kv.x + qv.y * kv.y + qv.z * kv.z + qv.w * kv.w;
            }
        }

#pragma unroll
        for (int qq = 0; qq < QPW; qq++) {
            float s = kin ? sc[qq] : -1e30f;
            float mt = s;
#pragma unroll
            for (int off = 16; off; off >>= 1)
                mt = fmaxf(mt, __shfl_xor_sync(0xffffffffu, mt, off));
            float mnew = fmaxf(mrun[qq], mt);
            float p = kin ? __expf(s - mnew) : 0.f;
            float ps = p;
#pragma unroll
            for (int off = 16; off; off >>= 1)
                ps += __shfl_xor_sync(0xffffffffu, ps, off);
            float alpha = __expf(mrun[qq] - mnew);
            lrun[qq] = lrun[qq] * alpha + ps;
            mrun[qq] = mnew;
            psh[warp][qq][lane] = p;
            o[qq][0] *= alpha; o[qq][1] *= alpha; o[qq][2] *= alpha;
        }
        __syncwarp();

#pragma unroll 8
        for (int j = 0; j < TK; j++) {
            float v0 = Vsh[j][lane];
            float v1 = Vsh[j][lane + 32];
            float v2 = (lane < D - 64) ? Vsh[j][lane + 64] : 0.f;
#pragma unroll
            for (int qq = 0; qq < QPW; qq++) {
                float pj = psh[warp][qq][j];
                o[qq][0] += pj * v0;
                o[qq][1] += pj * v1;
                o[qq][2] += pj * v2;
            }
        }
        __syncwarp();
    }

#pragma unroll
    for (int qq = 0; qq < QPW; qq++) {
        int qi = q0 + qq;
        if (qi >= S) continue;
        float inv = 1.f / lrun[qq];
        float* op = &out[((size_t)(b * S + qi)) * E + h * D];
        op[lane]      = o[qq][0] * inv;
        op[lane + 32] = o[qq][1] * inv;
        if (lane < D - 64) op[lane + 64] = o[qq][2] * inv;
    }
}

// ---------------------------------------------------------------------------
// Launch
// ---------------------------------------------------------------------------
extern "C" void kernel_launch(void* const* d_in, const int* in_sizes, int n_in,
                              void* d_out, int out_size)
{
    const float* hs   = (const float*)d_in[0];
    const float* fcos = (const float*)d_in[1];
    const float* fsin = (const float*)d_in[2];
    const float* Wq   = (const float*)d_in[3];
    const float* bq   = (const float*)d_in[4];
    const float* Wk   = (const float*)d_in[5];
    const float* bk   = (const float*)d_in[6];
    const float* Wv   = (const float*)d_in[7];
    const float* bv   = (const float*)d_in[8];
    const float* Wo   = (const float*)d_in[9];
    const float* bo   = (const float*)d_in[10];
    float* out = (float*)d_out;

    float *pq, *pk, *pv, *pa;
    cudaGetSymbolAddress((void**)&pq, g_q);
    cudaGetSymbolAddress((void**)&pk, g_k);
    cudaGetSymbolAddress((void**)&pv, g_v);
    cudaGetSymbolAddress((void**)&pa, g_attn);

    dim3 gg((M_ROWS + BM - 1) / BM, E / BN, 1);   // 65 x 11
    gemm_bias_rope<<<gg, 256>>>(hs, Wq, bq, fcos, fsin, pq, M_ROWS, 1);
    gemm_bias_rope<<<gg, 256>>>(hs, Wk, bk, fcos, fsin, pk, M_ROWS, 1);
    gemm_bias_rope<<<gg, 256>>>(hs, Wv, bv, fcos, fsin, pv, M_ROWS, 0);

    dim3 ga((S + NW * QPW - 1) / (NW * QPW), B * H, 1);  // 33 x 128
    flash_attn<<<ga, 256>>>(pq, pk, pv, pa);

    gemm_bias_rope<<<gg, 256>>>(pa, Wo, bo, fcos, fsin, out, M_ROWS, 0);
}

// round 7
// speedup vs baseline: 2.4813x; 1.4263x over previous
#include <cuda_runtime.h>
#include <cuda_bf16.h>
#include <cstdint>
#include <math.h>

// Problem constants
#define B 8
#define S 1025
#define E 1408
#define H 16
#define D 88
#define D2 44
#define M_ROWS (B * S)          // 8200

// ---------------------------------------------------------------------------
// Scratch (allocation-free: __device__ globals)
// ---------------------------------------------------------------------------
__device__ float g_q[(size_t)M_ROWS * E];
__device__ float g_k[(size_t)M_ROWS * E];
__device__ float g_v[(size_t)M_ROWS * E];
__device__ float g_attn[(size_t)M_ROWS * E];
__device__ __nv_bfloat16 g_ahi[(size_t)M_ROWS * E];
__device__ __nv_bfloat16 g_alo[(size_t)M_ROWS * E];
__device__ __nv_bfloat16 g_whi[(size_t)E * E];
__device__ __nv_bfloat16 g_wlo[(size_t)E * E];

// ---------------------------------------------------------------------------
// Split fp32 -> (hi, lo) bf16 pair.  x = hi + lo + O(2^-18 x)
// ---------------------------------------------------------------------------
__global__ __launch_bounds__(256)
void split_bf16(const float* __restrict__ x,
                __nv_bfloat16* __restrict__ hi,
                __nv_bfloat16* __restrict__ lo,
                size_t n)
{
    size_t i = ((size_t)blockIdx.x * 256 + threadIdx.x) * 4;
    if (i >= n) return;
    float4 v = *(const float4*)(x + i);
    __nv_bfloat16 h0 = __float2bfloat16(v.x);
    __nv_bfloat16 h1 = __float2bfloat16(v.y);
    __nv_bfloat16 h2 = __float2bfloat16(v.z);
    __nv_bfloat16 h3 = __float2bfloat16(v.w);
    __nv_bfloat16 l0 = __float2bfloat16(v.x - __bfloat162float(h0));
    __nv_bfloat16 l1 = __float2bfloat16(v.y - __bfloat162float(h1));
    __nv_bfloat16 l2 = __float2bfloat16(v.z - __bfloat162float(h2));
    __nv_bfloat16 l3 = __float2bfloat16(v.w - __bfloat162float(h3));
    __nv_bfloat162* hp = (__nv_bfloat162*)(hi + i);
    __nv_bfloat162* lp = (__nv_bfloat162*)(lo + i);
    hp[0] = __nv_bfloat162(h0, h1);
    hp[1] = __nv_bfloat162(h2, h3);
    lp[0] = __nv_bfloat162(l0, l1);
    lp[1] = __nv_bfloat162(l2, l3);
}

// ---------------------------------------------------------------------------
// HMMA helpers (baseline PTX mma.sync — compiles for plain sm_103)
// ---------------------------------------------------------------------------
__device__ __forceinline__ void mma16816(float* c, const uint32_t* a,
                                         const uint32_t* b)
{
    asm volatile(
        "mma.sync.aligned.m16n8k16.row.col.f32.bf16.bf16.f32 "
        "{%0,%1,%2,%3}, {%4,%5,%6,%7}, {%8,%9}, {%0,%1,%2,%3};\n"
        : "+f"(c[0]), "+f"(c[1]), "+f"(c[2]), "+f"(c[3])
        : "r"(a[0]), "r"(a[1]), "r"(a[2]), "r"(a[3]),
          "r"(b[0]), "r"(b[1]));
}

__device__ __forceinline__ void cp16(uint32_t dst, const void* src, bool valid) {
    uint64_t g = __cvta_generic_to_global(src);
    uint32_t sz = valid ? 16u : 0u;
    asm volatile("cp.async.cg.shared.global [%0], [%1], 16, %2;\n"
                 :: "r"(dst), "l"(g), "r"(sz));
}

// ---------------------------------------------------------------------------
// HMMA GEMM: C[m][n] = sum_k A[m][k]*W[n][k] + bias[n], optional RoPE.
// Split-bf16: D += Ah*Wh + Ah*Wl + Al*Wh.
// CTA tile 128x128, BK=32, 8 warps (4x2), warp tile 32x64.
// Smem pitch 40 bf16 (80B) -> conflict-free fragment loads.
// ---------------------------------------------------------------------------
#define BKT 32
#define NSTG (E / BKT)            // 44
#define PITCH 40                  // bf16 elements per smem row
#define ARR_B (128 * PITCH * 2)   // 10240 B per array
#define STAGE_B (4 * ARR_B)       // Ah, Al, Wh, Wl = 40960 B
#define GEMM_SMEM (2 * STAGE_B)   // 81920 B

extern __shared__ char dsm[];

__device__ __forceinline__ void stage_loads(
    uint32_t smem, int s, int m0, int n0, int Mdim,
    const __nv_bfloat16* Ahi, const __nv_bfloat16* Alo,
    const __nv_bfloat16* Whi, const __nv_bfloat16* Wlo)
{
    const int tid = threadIdx.x;
    const int k0 = s * BKT;
    const uint32_t base = smem + (uint32_t)(s & 1) * STAGE_B;
#pragma unroll
    for (int i = 0; i < 8; i++) {
        int c = tid + i * 256;            // 0..2047
        int arr = c >> 9;                 // 0..3
        int rem = c & 511;
        int row = rem >> 2;               // 0..127
        int ch  = rem & 3;                // 16B chunk within 64B row
        uint32_t dst = base + (uint32_t)arr * ARR_B
                     + (uint32_t)row * (PITCH * 2) + (uint32_t)ch * 16;
        const __nv_bfloat16* src;
        int gr;
        bool valid = true;
        if (arr == 0)      { src = Ahi; gr = m0 + row; valid = gr < Mdim; }
        else if (arr == 1) { src = Alo; gr = m0 + row; valid = gr < Mdim; }
        else if (arr == 2) { src = Whi; gr = n0 + row; }
        else               { src = Wlo; gr = n0 + row; }
        if (!valid) gr = 0;
        cp16(dst, src + (size_t)gr * E + k0 + ch * 8, valid);
    }
    asm volatile("cp.async.commit_group;\n" ::: "memory");
}

__global__ __launch_bounds__(256)
void gemm_tc(const __nv_bfloat16* __restrict__ Ahi,
             const __nv_bfloat16* __restrict__ Alo,
             const __nv_bfloat16* __restrict__ Whi,
             const __nv_bfloat16* __restrict__ Wlo,
             const float* __restrict__ bias,
             const float* __restrict__ fcos,
             const float* __restrict__ fsin,
             float* __restrict__ C,
             int Mdim, int rope)
{
    uint32_t smem = (uint32_t)__cvta_generic_to_shared(dsm);
    const int tid    = threadIdx.x;
    const int wid    = tid >> 5;
    const int lane   = tid & 31;
    const int warp_m = wid & 3;       // 4 warps along M
    const int warp_n = wid >> 2;      // 2 warps along N
    const int g = lane >> 2;          // group id 0..7
    const int t = lane & 3;           // thread in group
    const int m0 = blockIdx.x * 128;
    const int n0 = blockIdx.y * 128;

    float acc[2][8][4];
#pragma unroll
    for (int mt = 0; mt < 2; mt++)
#pragma unroll
        for (int nt = 0; nt < 8; nt++)
#pragma unroll
            for (int e = 0; e < 4; e++) acc[mt][nt][e] = 0.f;

    stage_loads(smem, 0, m0, n0, Mdim, Ahi, Alo, Whi, Wlo);

    for (int s = 0; s < NSTG; s++) {
        if (s + 1 < NSTG) {
            stage_loads(smem, s + 1, m0, n0, Mdim, Ahi, Alo, Whi, Wlo);
            asm volatile("cp.async.wait_group 1;\n" ::: "memory");
        } else {
            asm volatile("cp.async.wait_group 0;\n" ::: "memory");
        }
        __syncthreads();

        const char* buf = dsm + (size_t)(s & 1) * STAGE_B;
        const char* sAh = buf;
        const char* sAl = buf + ARR_B;
        const char* sWh = buf + 2 * ARR_B;
        const char* sWl = buf + 3 * ARR_B;

#pragma unroll
        for (int ks = 0; ks < 2; ks++) {
            const int kc = ks * 16;
            uint32_t Ah[2][4], Al[2][4];
#pragma unroll
            for (int mt = 0; mt < 2; mt++) {
                const int r0 = warp_m * 32 + mt * 16 + g;
                const char* p0 = sAh + (size_t)r0 * (PITCH * 2);
                const char* p1 = sAh + (size_t)(r0 + 8) * (PITCH * 2);
                Ah[mt][0] = *(const uint32_t*)(p0 + (kc + t * 2) * 2);
                Ah[mt][1] = *(const uint32_t*)(p1 + (kc + t * 2) * 2);
                Ah[mt][2] = *(const uint32_t*)(p0 + (kc + 8 + t * 2) * 2);
                Ah[mt][3] = *(const uint32_t*)(p1 + (kc + 8 + t * 2) * 2);
                const char* q0 = sAl + (size_t)r0 * (PITCH * 2);
                const char* q1 = sAl + (size_t)(r0 + 8) * (PITCH * 2);
                Al[mt][0] = *(const uint32_t*)(q0 + (kc + t * 2) * 2);
                Al[mt][1] = *(const uint32_t*)(q1 + (kc + t * 2) * 2);
                Al[mt][2] = *(const uint32_t*)(q0 + (kc + 8 + t * 2) * 2);
                Al[mt][3] = *(const uint32_t*)(q1 + (kc + 8 + t * 2) * 2);
            }
#pragma unroll
            for (int nt = 0; nt < 8; nt++) {
                const int nr = warp_n * 64 + nt * 8 + g;
                const char* pb = sWh + (size_t)nr * (PITCH * 2);
                const char* qb = sWl + (size_t)nr * (PITCH * 2);
                uint32_t Bh[2], Bl[2];
                Bh[0] = *(const uint32_t*)(pb + (kc + t * 2) * 2);
                Bh[1] = *(const uint32_t*)(pb + (kc + 8 + t * 2) * 2);
                Bl[0] = *(const uint32_t*)(qb + (kc + t * 2) * 2);
                Bl[1] = *(const uint32_t*)(qb + (kc + 8 + t * 2) * 2);
#pragma unroll
                for (int mt = 0; mt < 2; mt++) {
                    mma16816(acc[mt][nt], Ah[mt], Bh);
                    mma16816(acc[mt][nt], Ah[mt], Bl);
                    mma16816(acc[mt][nt], Al[mt], Bh);
                }
            }
        }
        __syncthreads();
    }

    // Epilogue: bias + optional RoPE. c0,c1 -> (row, col..col+1); c2,c3 -> row+8.
#pragma unroll
    for (int mt = 0; mt < 2; mt++) {
        const int mA = m0 + warp_m * 32 + mt * 16 + g;
        const int mB = mA + 8;
        const int sA = mA % S;
        const int sB = mB % S;
#pragma unroll
        for (int nt = 0; nt < 8; nt++) {
            const int n = n0 + warp_n * 64 + nt * 8 + t * 2;
            const float b0 = bias[n];
            const float b1 = bias[n + 1];
            float v0 = acc[mt][nt][0] + b0;
            float v1 = acc[mt][nt][1] + b1;
            float v2 = acc[mt][nt][2] + b0;
            float v3 = acc[mt][nt][3] + b1;
            if (rope) {
                const int i0 = (n % D) >> 1;
                float cA = fcos[sA * D2 + i0], snA = fsin[sA * D2 + i0];
                float cB = fcos[sB * D2 + i0], snB = fsin[sB * D2 + i0];
                float t0 = v0 * cA - v1 * snA;
                v1       = v0 * snA + v1 * cA;
                v0 = t0;
                float t2 = v2 * cB - v3 * snB;
                v3       = v2 * snB + v3 * cB;
                v2 = t2;
            }
            if (mA < Mdim) *(float2*)&C[(size_t)mA * E + n] = make_float2(v0, v1);
            if (mB < Mdim) *(float2*)&C[(size_t)mB * E + n] = make_float2(v2, v3);
        }
    }
}

// ---------------------------------------------------------------------------
// Flash attention (proven R2 kernel): 4 queries/warp, 32-key tiles.
// ---------------------------------------------------------------------------
#define TK 32
#define NW 8
#define QPW 4
#define KP 92

__global__ __launch_bounds__(256)
void flash_attn(const float* __restrict__ q,
                const float* __restrict__ k,
                const float* __restrict__ v,
                float* __restrict__ out)
{
    __shared__ float Ksh[TK][KP];
    __shared__ float Vsh[TK][KP];
    __shared__ float qsh[NW][QPW][KP];
    __shared__ float psh[NW][QPW][TK];

    const int bh = blockIdx.y;
    const int b  = bh / H;
    const int h  = bh % H;
    const int warp = threadIdx.x >> 5;
    const int lane = threadIdx.x & 31;
    const int q0 = (blockIdx.x * NW + warp) * QPW;

    const float scale = rsqrtf((float)D);

#pragma unroll
    for (int qq = 0; qq < QPW; qq++) {
        int qi = q0 + qq;
        if (qi < S) {
            const float* qp = &q[((size_t)(b * S + qi)) * E + h * D];
            for (int d = lane; d < D; d += 32)
                qsh[warp][qq][d] = qp[d] * scale;
        } else {
            for (int d = lane; d < D; d += 32)
                qsh[warp][qq][d] = 0.f;
        }
    }

    float mrun[QPW], lrun[QPW], o[QPW][3];
#pragma unroll
    for (int qq = 0; qq < QPW; qq++) {
        mrun[qq] = -1e30f; lrun[qq] = 0.f;
        o[qq][0] = o[qq][1] = o[qq][2] = 0.f;
    }

    for (int t0 = 0; t0 < S; t0 += TK) {
        __syncthreads();

        for (int idx = threadIdx.x; idx < TK * (D / 4); idx += 256) {
            int r  = idx / (D / 4);
            int c4 = idx % (D / 4);
            int key = t0 + r;
            float4 kv, vv;
            if (key < S) {
                size_t base = ((size_t)(b * S + key)) * E + h * D + c4 * 4;
                kv = *(const float4*)&k[base];
                vv = *(const float4*)&v[base];
            } else {
                kv = make_float4(0.f, 0.f, 0.f, 0.f);
                vv = kv;
            }
            *(float4*)&Ksh[r][c4 * 4] = kv;
            *(float4*)&Vsh[r][c4 * 4] = vv;
        }
        __syncthreads();

        const int key = t0 + lane;
        const bool kin = (key < S);

        float sc[QPW] = {0.f, 0.f, 0.f, 0.f};
#pragma unroll
        for (int c = 0; c < D / 4; c++) {
            float4 kv = *(const float4*)&Ksh[lane][c * 4];
#pragma unroll
            for (int qq = 0; qq < QPW; qq++) {
                float4 qv = *(const float4*)&qsh[warp][qq][c * 4];
                sc[qq] += qv.x * kv.x + qv.y * kv.y + qv.z * kv.z + qv.w * kv.w;
            }
        }

#pragma unroll
        for (int qq = 0; qq < QPW; qq++) {
            float s = kin ? sc[qq] : -1e30f;
            float mt = s;
#pragma unroll
            for (int off = 16; off; off >>= 1)
                mt = fmaxf(mt, __shfl_xor_sync(0xffffffffu, mt, off));
            float mnew = fmaxf(mrun[qq], mt);
            float p = kin ? __expf(s - mnew) : 0.f;
            float ps = p;
#pragma unroll
            for (int off = 16; off; off >>= 1)
                ps += __shfl_xor_sync(0xffffffffu, ps, off);
            float alpha = __expf(mrun[qq] - mnew);
            lrun[qq] = lrun[qq] * alpha + ps;
            mrun[qq] = mnew;
            psh[warp][qq][lane] = p;
            o[qq][0] *= alpha; o[qq][1] *= alpha; o[qq][2] *= alpha;
        }
        __syncwarp();

#pragma unroll 8
        for (int j = 0; j < TK; j++) {
            float v0 = Vsh[j][lane];
            float v1 = Vsh[j][lane + 32];
            float v2 = (lane < D - 64) ? Vsh[j][lane + 64] : 0.f;
#pragma unroll
            for (int qq = 0; qq < QPW; qq++) {
                float pj = psh[warp][qq][j];
                o[qq][0] += pj * v0;
                o[qq][1] += pj * v1;
                o[qq][2] += pj * v2;
            }
        }
        __syncwarp();
    }

#pragma unroll
    for (int qq = 0; qq < QPW; qq++) {
        int qi = q0 + qq;
        if (qi >= S) continue;
        float inv = 1.f / lrun[qq];
        float* op = &out[((size_t)(b * S + qi)) * E + h * D];
        op[lane]      = o[qq][0] * inv;
        op[lane + 32] = o[qq][1] * inv;
        if (lane < D - 64) op[lane + 64] = o[qq][2] * inv;
    }
}

// ---------------------------------------------------------------------------
// Launch
// ---------------------------------------------------------------------------
extern "C" void kernel_launch(void* const* d_in, const int* in_sizes, int n_in,
                              void* d_out, int out_size)
{
    const float* hs   = (const float*)d_in[0];
    const float* fcos = (const float*)d_in[1];
    const float* fsin = (const float*)d_in[2];
    const float* Wq   = (const float*)d_in[3];
    const float* bq   = (const float*)d_in[4];
    const float* Wk   = (const float*)d_in[5];
    const float* bk   = (const float*)d_in[6];
    const float* Wv   = (const float*)d_in[7];
    const float* bv   = (const float*)d_in[8];
    const float* Wo   = (const float*)d_in[9];
    const float* bo   = (const float*)d_in[10];
    float* out = (float*)d_out;

    float *pq, *pk, *pv, *pa;
    __nv_bfloat16 *pah, *pal, *pwh, *pwl;
    cudaGetSymbolAddress((void**)&pq, g_q);
    cudaGetSymbolAddress((void**)&pk, g_k);
    cudaGetSymbolAddress((void**)&pv, g_v);
    cudaGetSymbolAddress((void**)&pa, g_attn);
    cudaGetSymbolAddress((void**)&pah, g_ahi);
    cudaGetSymbolAddress((void**)&pal, g_alo);
    cudaGetSymbolAddress((void**)&pwh, g_whi);
    cudaGetSymbolAddress((void**)&pwl, g_wlo);

    cudaFuncSetAttribute(gemm_tc, cudaFuncAttributeMaxDynamicSharedMemorySize,
                         GEMM_SMEM);

    const size_t nA = (size_t)M_ROWS * E;
    const size_t nW = (size_t)E * E;
    const int cbA = (int)((nA / 4 + 255) / 256);
    const int cbW = (int)((nW / 4 + 255) / 256);

    dim3 gg((M_ROWS + 127) / 128, E / 128, 1);   // 65 x 11

    // hidden states -> bf16 split
    split_bf16<<<cbA, 256>>>(hs, pah, pal, nA);

    // Q
    split_bf16<<<cbW, 256>>>(Wq, pwh, pwl, nW);
    gemm_tc<<<gg, 256, GEMM_SMEM>>>(pah, pal, pwh, pwl, bq, fcos, fsin, pq, M_ROWS, 1);
    // K
    split_bf16<<<cbW, 256>>>(Wk, pwh, pwl, nW);
    gemm_tc<<<gg, 256, GEMM_SMEM>>>(pah, pal, pwh, pwl, bk, fcos, fsin, pk, M_ROWS, 1);
    // V
    split_bf16<<<cbW, 256>>>(Wv, pwh, pwl, nW);
    gemm_tc<<<gg, 256, GEMM_SMEM>>>(pah, pal, pwh, pwl, bv, fcos, fsin, pv, M_ROWS, 0);

    // Attention
    dim3 ga((S + NW * QPW - 1) / (NW * QPW), B * H, 1);  // 33 x 128
    flash_attn<<<ga, 256>>>(pq, pk, pv, pa);

    // O projection
    split_bf16<<<cbA, 256>>>(pa, pah, pal, nA);
    split_bf16<<<cbW, 256>>>(Wo, pwh, pwl, nW);
    gemm_tc<<<gg, 256, GEMM_SMEM>>>(pah, pal, pwh, pwl, bo, fcos, fsin, out, M_ROWS, 0);
}